// round 8
// baseline (speedup 1.0000x reference)
#include <cuda_runtime.h>
#include <math_constants.h>

// Shapes fixed by the problem
#define B_  32
#define T_  12
#define N_  512
#define F_  64
#define H_  64

#define BLOCKS 512
#define THREADS 256
#define WARPS   8
#define PAIRS_PER_WARP  4      // 512 * 8 * 4 = 16384 = B*N
#define PAIRS_PER_BLOCK 32

// Per-block partial 12x12 gram matrices (overwritten every launch; no zeroing needed)
__device__ float g_partial[BLOCKS * 144];
// Ticket: zero at module load; last block resets to 0 each launch -> every
// graph replay starts clean (deterministic).
__device__ unsigned int g_ticket;

__global__ __launch_bounds__(THREADS) void fft_sel_fused(
    const float* __restrict__ x,   // [B,T,N,F]
    const float* __restrict__ Wq,  // [F,H]
    const float* __restrict__ bq,  // [H]
    const float* __restrict__ Wk,  // [F,H]
    const float* __restrict__ bk,  // [H]
    float* __restrict__ out, int out_n)
{
    __shared__ float s_wq[F_], s_wk[F_];
    __shared__ float s_bsum[2];
    __shared__ float s_q[PAIRS_PER_BLOCK * T_];   // 32 pairs x 12 t
    __shared__ float s_k[PAIRS_PER_BLOCK * T_];
    __shared__ float s_part[7][144];
    __shared__ float s_score[144];
    __shared__ bool  s_last;

    const int tid  = threadIdx.x;
    const int wid  = tid >> 5;
    const int lane = tid & 31;

    // ---- Coalesced pre-sum of weights over H (exact FFT/irfft/mean-H collapse) ----
    {
#pragma unroll
        for (int r = 0; r < 8; r++) {
            const int f = wid * 8 + r;
            float aq = Wq[f * H_ + lane] + Wq[f * H_ + 32 + lane];
            float ak = Wk[f * H_ + lane] + Wk[f * H_ + 32 + lane];
#pragma unroll
            for (int s = 16; s >= 1; s >>= 1) {
                aq += __shfl_xor_sync(0xffffffffu, aq, s);
                ak += __shfl_xor_sync(0xffffffffu, ak, s);
            }
            if (lane == 0) { s_wq[f] = aq; s_wk[f] = ak; }
        }
        if (wid == 0) {
            float a = bq[lane] + bq[32 + lane];
#pragma unroll
            for (int s = 16; s >= 1; s >>= 1) a += __shfl_xor_sync(0xffffffffu, a, s);
            if (lane == 0) s_bsum[0] = a;
        } else if (wid == 1) {
            float a = bk[lane] + bk[32 + lane];
#pragma unroll
            for (int s = 16; s >= 1; s >>= 1) a += __shfl_xor_sync(0xffffffffu, a, s);
            if (lane == 0) s_bsum[1] = a;
        }
    }
    __syncthreads();

    // ---- 4-lane-group streaming scheme ----
    // Warp = 8 groups of 4 lanes. Group g handles one (pair,row) slot per
    // slot-iter; lane q of a group loads interleaved float4s q, q+4, q+8, q+12
    // of the 64-float row (4 independent LDG.128 per lane per slot).
    const int g = lane >> 2;
    const int q = lane & 3;

    // Preload this lane's weight segments (interleaved positions)
    float4 wq4r[4], wk4r[4];
#pragma unroll
    for (int i = 0; i < 4; i++) {
        wq4r[i] = ((const float4*)s_wq)[q + 4 * i];
        wk4r[i] = ((const float4*)s_wk)[q + 4 * i];
    }
    const float bqs = s_bsum[0];
    const float bks = s_bsum[1];

    const float4* __restrict__ x4 = (const float4*)x;
    const int warpPairBase = (blockIdx.x * WARPS + wid) * PAIRS_PER_WARP;

    // 2 super-iters x 2 pairs; each super-iter covers 24 (pair,row) slots
    // in 3 slot-iters of 8 groups.
#pragma unroll
    for (int su = 0; su < PAIRS_PER_WARP / 2; su++) {
        const int pbase = warpPairBase + 2 * su;

#pragma unroll
        for (int it = 0; it < 3; it++) {
            const int slot = it * 8 + g;          // 0..23
            const int pr   = slot / 12;           // 0 or 1
            const int row  = slot - pr * 12;      // t index
            const int gp   = pbase + pr;
            const int b    = gp >> 9;
            const int n    = gp & 511;
            const size_t rowbase = ((size_t)(b * T_ + row) * N_ + n) * 16;

            float4 v0 = x4[rowbase + q];
            float4 v1 = x4[rowbase + q + 4];
            float4 v2 = x4[rowbase + q + 8];
            float4 v3 = x4[rowbase + q + 12];

            float aq = v0.x * wq4r[0].x + v0.y * wq4r[0].y + v0.z * wq4r[0].z + v0.w * wq4r[0].w
                     + v1.x * wq4r[1].x + v1.y * wq4r[1].y + v1.z * wq4r[1].z + v1.w * wq4r[1].w
                     + v2.x * wq4r[2].x + v2.y * wq4r[2].y + v2.z * wq4r[2].z + v2.w * wq4r[2].w
                     + v3.x * wq4r[3].x + v3.y * wq4r[3].y + v3.z * wq4r[3].z + v3.w * wq4r[3].w;
            float ak = v0.x * wk4r[0].x + v0.y * wk4r[0].y + v0.z * wk4r[0].z + v0.w * wk4r[0].w
                     + v1.x * wk4r[1].x + v1.y * wk4r[1].y + v1.z * wk4r[1].z + v1.w * wk4r[1].w
                     + v2.x * wk4r[2].x + v2.y * wk4r[2].y + v2.z * wk4r[2].z + v2.w * wk4r[2].w
                     + v3.x * wk4r[3].x + v3.y * wk4r[3].y + v3.z * wk4r[3].z + v3.w * wk4r[3].w;

            // 4-lane reduction, 3 shuffles, depth 2:
            // stage 1: xor-2 partial sums; stage 2: cross-swap aq/ak via one shuffle.
            const float aq2 = aq + __shfl_xor_sync(0xffffffffu, aq, 2);
            const float ak2 = ak + __shfl_xor_sync(0xffffffffu, ak, 2);
            const float vsel = (q & 1) ? aq2 : ak2;
            const float toth = __shfl_xor_sync(0xffffffffu, vsel, 1);

            const int e = wid * PAIRS_PER_WARP + 2 * su + pr;   // 0..31
            if (q == 0) s_q[e * T_ + row] = aq2 + toth + bqs;   // aq[0,2]+aq[1,3]
            else if (q == 1) s_k[e * T_ + row] = ak2 + toth + bks;
        }
    }
    __syncthreads();

    // ---- Block-local 12x12 gram over the 32 staged (b,n) pairs ----
    if (tid < 144) {
        const int i = tid / 12;
        const int j = tid - i * 12;
        float acc = 0.f;
#pragma unroll 8
        for (int e = 0; e < PAIRS_PER_BLOCK; e++)
            acc += s_q[e * T_ + i] * s_k[e * T_ + j];
        g_partial[blockIdx.x * 144 + tid] = acc;
    }

    // ---- Last-block ticket ----
    __threadfence();          // publish g_partial
    __syncthreads();
    if (tid == 0) {
        unsigned int old = atomicAdd(&g_ticket, 1u);
        s_last = (old == BLOCKS - 1u);
    }
    __syncthreads();
    if (!s_last) return;

    __threadfence();          // acquire all blocks' g_partial

    // ---- Final reduction: 512 partials -> 12x12 scores ----
    // g_partial viewed as [BLOCKS][36] float4; 252 threads = 7 slices x 36 groups.
    if (tid < 252) {
        const int s  = tid / 36;
        const int g4 = tid - s * 36;
        const float4* gp4 = (const float4*)g_partial;
        float4 acc = make_float4(0.f, 0.f, 0.f, 0.f);
#pragma unroll 4
        for (int e = s; e < BLOCKS; e += 7) {
            const float4 v = gp4[e * 36 + g4];
            acc.x += v.x; acc.y += v.y; acc.z += v.z; acc.w += v.w;
        }
        s_part[s][g4 * 4 + 0] = acc.x;
        s_part[s][g4 * 4 + 1] = acc.y;
        s_part[s][g4 * 4 + 2] = acc.z;
        s_part[s][g4 * 4 + 3] = acc.w;
    }
    __syncthreads();

    if (tid < 144) {
        float a = 0.f;
#pragma unroll
        for (int s = 0; s < 7; s++) a += s_part[s][tid];
        // mean over (B, N, H) = / (32*512*64)
        s_score[tid] = a * (1.0f / 1048576.0f);
    }
    __syncthreads();

    if (tid == 0) g_ticket = 0u;   // reset for next graph replay

    // ---- Row-wise top-k (tau from out_size), jax tie-break = lowest index ----
    int tau;
    bool write_idx;
    if (out_n >= 2 * T_ && (out_n % (2 * T_)) == 0) {
        tau = out_n / (2 * T_);
        write_idx = true;
    } else {
        tau = out_n / T_;
        write_idx = false;
    }
    if (tau > T_) tau = T_;

    if (tid < T_) {
        const int i = tid;
        float v[T_];
#pragma unroll
        for (int j = 0; j < T_; j++) v[j] = s_score[i * 12 + j];
        unsigned usedmask = 0u;
        for (int r = 0; r < tau; r++) {
            float best = -CUDART_INF_F;
            int bj = 0;
#pragma unroll
            for (int j = 0; j < T_; j++) {
                bool ok = ((usedmask >> j) & 1u) == 0u && v[j] > best;
                if (ok) { best = v[j]; bj = j; }
            }
            usedmask |= (1u << bj);
            out[i * tau + r] = best;
            if (write_idx) out[T_ * tau + i * tau + r] = (float)bj;
        }
    }
}

extern "C" void kernel_launch(void* const* d_in, const int* in_sizes, int n_in,
                              void* d_out, int out_size)
{
    const float* x  = (const float*)d_in[0];
    const float* Wq = (const float*)d_in[1];
    const float* bq = (const float*)d_in[2];
    const float* Wk = (const float*)d_in[3];
    const float* bk = (const float*)d_in[4];
    (void)in_sizes; (void)n_in;

    fft_sel_fused<<<BLOCKS, THREADS>>>(x, Wq, bq, Wk, bk, (float*)d_out, out_size);
}

// round 9
// speedup vs baseline: 1.2424x; 1.2424x over previous
#include <cuda_runtime.h>
#include <math_constants.h>

// Shapes fixed by the problem
#define B_  32
#define T_  12
#define N_  512
#define F_  64
#define H_  64

#define BLOCKS 256
#define THREADS 256
#define WARPS   8
#define PAIRS_PER_WARP  8      // 256 * 8 * 8 = 16384 = B*N
#define PAIRS_PER_BLOCK 64

// Per-block partial 12x12 gram matrices (overwritten every launch; no zeroing needed)
__device__ float g_partial[BLOCKS * 144];
// Ticket: zero at module load; last block resets to 0 each launch -> every
// graph replay starts clean (deterministic).
__device__ unsigned int g_ticket;

__global__ __launch_bounds__(THREADS) void fft_sel_fused(
    const float* __restrict__ x,   // [B,T,N,F]
    const float* __restrict__ Wq,  // [F,H]
    const float* __restrict__ bq,  // [H]
    const float* __restrict__ Wk,  // [F,H]
    const float* __restrict__ bk,  // [H]
    float* __restrict__ out, int out_n)
{
    __shared__ float s_wq[F_], s_wk[F_];
    __shared__ float s_bsum[2];
    __shared__ float s_q[PAIRS_PER_BLOCK * T_];   // 64 pairs x 12 t
    __shared__ float s_k[PAIRS_PER_BLOCK * T_];
    __shared__ float s_part[7][144];
    __shared__ float s_score[144];
    __shared__ bool  s_last;

    const int tid  = threadIdx.x;
    const int wid  = tid >> 5;
    const int lane = tid & 31;

    // ---- Coalesced pre-sum of weights over H (exact FFT/irfft/mean-H collapse) ----
    {
#pragma unroll
        for (int r = 0; r < 8; r++) {
            const int f = wid * 8 + r;
            float aq = Wq[f * H_ + lane] + Wq[f * H_ + 32 + lane];
            float ak = Wk[f * H_ + lane] + Wk[f * H_ + 32 + lane];
#pragma unroll
            for (int s = 16; s >= 1; s >>= 1) {
                aq += __shfl_xor_sync(0xffffffffu, aq, s);
                ak += __shfl_xor_sync(0xffffffffu, ak, s);
            }
            if (lane == 0) { s_wq[f] = aq; s_wk[f] = ak; }
        }
        if (wid == 0) {
            float a = bq[lane] + bq[32 + lane];
#pragma unroll
            for (int s = 16; s >= 1; s >>= 1) a += __shfl_xor_sync(0xffffffffu, a, s);
            if (lane == 0) s_bsum[0] = a;
        } else if (wid == 1) {
            float a = bk[lane] + bk[32 + lane];
#pragma unroll
            for (int s = 16; s >= 1; s >>= 1) a += __shfl_xor_sync(0xffffffffu, a, s);
            if (lane == 0) s_bsum[1] = a;
        }
    }
    __syncthreads();

    // ---- 4-lane-group streaming scheme, front-batched loads ----
    // Warp = 8 groups of 4 lanes. Per super-iter (2 pairs = 24 slots), each
    // group handles 3 slots; lane q of a group loads interleaved float4s
    // q, q+4, q+8, q+12 of each 64-float row. All 12 loads are issued before
    // any reduction -> 12 outstanding LDG.128 per lane.
    const int g = lane >> 2;
    const int q = lane & 3;

    float4 wq4r[4], wk4r[4];
#pragma unroll
    for (int i = 0; i < 4; i++) {
        wq4r[i] = ((const float4*)s_wq)[q + 4 * i];
        wk4r[i] = ((const float4*)s_wk)[q + 4 * i];
    }
    const float bqs = s_bsum[0];
    const float bks = s_bsum[1];

    const float4* __restrict__ x4 = (const float4*)x;
    const int warpPairBase = (blockIdx.x * WARPS + wid) * PAIRS_PER_WARP;

#pragma unroll
    for (int su = 0; su < PAIRS_PER_WARP / 2; su++) {
        const int pbase = warpPairBase + 2 * su;

        float4 v[3][4];
        int row_[3], e_[3];

        // ---- Load phase: 12 independent LDG.128 ----
#pragma unroll
        for (int it = 0; it < 3; it++) {
            const int slot = it * 8 + g;          // 0..23
            const int pr   = slot / 12;           // 0 or 1
            const int row  = slot - pr * 12;      // t index
            const int gp   = pbase + pr;
            const int b    = gp >> 9;
            const int n    = gp & 511;
            const size_t rowbase = ((size_t)(b * T_ + row) * N_ + n) * 16;
            v[it][0] = x4[rowbase + q];
            v[it][1] = x4[rowbase + q + 4];
            v[it][2] = x4[rowbase + q + 8];
            v[it][3] = x4[rowbase + q + 12];
            row_[it] = row;
            e_[it]   = wid * PAIRS_PER_WARP + 2 * su + pr;   // 0..63
        }

        // ---- Reduce phase: 3 independent chains (latencies overlap) ----
#pragma unroll
        for (int it = 0; it < 3; it++) {
            float aq = v[it][0].x * wq4r[0].x + v[it][0].y * wq4r[0].y + v[it][0].z * wq4r[0].z + v[it][0].w * wq4r[0].w
                     + v[it][1].x * wq4r[1].x + v[it][1].y * wq4r[1].y + v[it][1].z * wq4r[1].z + v[it][1].w * wq4r[1].w
                     + v[it][2].x * wq4r[2].x + v[it][2].y * wq4r[2].y + v[it][2].z * wq4r[2].z + v[it][2].w * wq4r[2].w
                     + v[it][3].x * wq4r[3].x + v[it][3].y * wq4r[3].y + v[it][3].z * wq4r[3].z + v[it][3].w * wq4r[3].w;
            float ak = v[it][0].x * wk4r[0].x + v[it][0].y * wk4r[0].y + v[it][0].z * wk4r[0].z + v[it][0].w * wk4r[0].w
                     + v[it][1].x * wk4r[1].x + v[it][1].y * wk4r[1].y + v[it][1].z * wk4r[1].z + v[it][1].w * wk4r[1].w
                     + v[it][2].x * wk4r[2].x + v[it][2].y * wk4r[2].y + v[it][2].z * wk4r[2].z + v[it][2].w * wk4r[2].w
                     + v[it][3].x * wk4r[3].x + v[it][3].y * wk4r[3].y + v[it][3].z * wk4r[3].z + v[it][3].w * wk4r[3].w;

            // 4-lane reduction, 3 shuffles, depth 2
            const float aq2 = aq + __shfl_xor_sync(0xffffffffu, aq, 2);
            const float ak2 = ak + __shfl_xor_sync(0xffffffffu, ak, 2);
            const float vsel = (q & 1) ? aq2 : ak2;
            const float toth = __shfl_xor_sync(0xffffffffu, vsel, 1);

            if (q == 0) s_q[e_[it] * T_ + row_[it]] = aq2 + toth + bqs;
            else if (q == 1) s_k[e_[it] * T_ + row_[it]] = ak2 + toth + bks;
        }
    }
    __syncthreads();

    // ---- Block-local 12x12 gram over the 64 staged (b,n) pairs ----
    if (tid < 144) {
        const int i = tid / 12;
        const int j = tid - i * 12;
        float acc = 0.f;
#pragma unroll 8
        for (int e = 0; e < PAIRS_PER_BLOCK; e++)
            acc += s_q[e * T_ + i] * s_k[e * T_ + j];
        g_partial[blockIdx.x * 144 + tid] = acc;
    }

    // ---- Last-block ticket ----
    __threadfence();          // publish g_partial
    __syncthreads();
    if (tid == 0) {
        unsigned int old = atomicAdd(&g_ticket, 1u);
        s_last = (old == BLOCKS - 1u);
    }
    __syncthreads();
    if (!s_last) return;

    __threadfence();          // acquire all blocks' g_partial

    // ---- Final reduction: 256 partials -> 12x12 scores ----
    // g_partial viewed as [BLOCKS][36] float4; 252 threads = 7 slices x 36 groups.
    if (tid < 252) {
        const int s  = tid / 36;
        const int g4 = tid - s * 36;
        const float4* gp4 = (const float4*)g_partial;
        float4 acc = make_float4(0.f, 0.f, 0.f, 0.f);
#pragma unroll 4
        for (int e = s; e < BLOCKS; e += 7) {
            const float4 vv = gp4[e * 36 + g4];
            acc.x += vv.x; acc.y += vv.y; acc.z += vv.z; acc.w += vv.w;
        }
        s_part[s][g4 * 4 + 0] = acc.x;
        s_part[s][g4 * 4 + 1] = acc.y;
        s_part[s][g4 * 4 + 2] = acc.z;
        s_part[s][g4 * 4 + 3] = acc.w;
    }
    __syncthreads();

    if (tid < 144) {
        float a = 0.f;
#pragma unroll
        for (int s = 0; s < 7; s++) a += s_part[s][tid];
        // mean over (B, N, H) = / (32*512*64)
        s_score[tid] = a * (1.0f / 1048576.0f);
    }
    __syncthreads();

    if (tid == 0) g_ticket = 0u;   // reset for next graph replay

    // ---- Row-wise top-k (tau from out_size), jax tie-break = lowest index ----
    int tau;
    bool write_idx;
    if (out_n >= 2 * T_ && (out_n % (2 * T_)) == 0) {
        tau = out_n / (2 * T_);
        write_idx = true;
    } else {
        tau = out_n / T_;
        write_idx = false;
    }
    if (tau > T_) tau = T_;

    if (tid < T_) {
        const int i = tid;
        float v[T_];
#pragma unroll
        for (int j = 0; j < T_; j++) v[j] = s_score[i * 12 + j];
        unsigned usedmask = 0u;
        for (int r = 0; r < tau; r++) {
            float best = -CUDART_INF_F;
            int bj = 0;
#pragma unroll
            for (int j = 0; j < T_; j++) {
                bool ok = ((usedmask >> j) & 1u) == 0u && v[j] > best;
                if (ok) { best = v[j]; bj = j; }
            }
            usedmask |= (1u << bj);
            out[i * tau + r] = best;
            if (write_idx) out[T_ * tau + i * tau + r] = (float)bj;
        }
    }
}

extern "C" void kernel_launch(void* const* d_in, const int* in_sizes, int n_in,
                              void* d_out, int out_size)
{
    const float* x  = (const float*)d_in[0];
    const float* Wq = (const float*)d_in[1];
    const float* bq = (const float*)d_in[2];
    const float* Wk = (const float*)d_in[3];
    const float* bk = (const float*)d_in[4];
    (void)in_sizes; (void)n_in;

    fft_sel_fused<<<BLOCKS, THREADS>>>(x, Wq, bq, Wk, bk, (float*)d_out, out_size);
}